// round 1
// baseline (speedup 1.0000x reference)
#include <cuda_runtime.h>

// Fused NeRF positional-encoding + 27x32 MLP + 32x1 head, fp32.
// Strategy: 2 points per thread, all math packed via Blackwell f32x2 FMA
// (fma.rn.f32x2 — 2x FP32 throughput, PTX-only). Weights duplicated (w,w)
// in shared memory so each LDS.64 broadcast feeds one packed FMA.
// sin/cos via branch-free Cody-Waite reduction + minimax polys (FMA pipe,
// immune to fast-math, accurate to ~1e-7 for |arg| < ~1e4; max arg here
// ~5.3*1024 ~ 5400).

typedef unsigned long long u64;

#define TPB 256
#define NIN 27
#define HID 32

__device__ __forceinline__ u64 pack2(float a, float b) {
    u64 r; asm("mov.b64 %0, {%1,%2};" : "=l"(r) : "f"(a), "f"(b)); return r;
}
__device__ __forceinline__ void unpack2(u64 v, float& a, float& b) {
    asm("mov.b64 {%0,%1}, %2;" : "=f"(a), "=f"(b) : "l"(v));
}
__device__ __forceinline__ u64 fma2(u64 a, u64 b, u64 c) {
    u64 d; asm("fma.rn.f32x2 %0, %1, %2, %3;" : "=l"(d) : "l"(a), "l"(b), "l"(c)); return d;
}
__device__ __forceinline__ u64 mul2(u64 a, u64 b) {
    u64 d; asm("mul.rn.f32x2 %0, %1, %2;" : "=l"(d) : "l"(a), "l"(b)); return d;
}
#define K2(v) pack2((v), (v))

// Packed sincos of two independent args. Cody-Waite 3-term pi/2 reduction
// (exact fma products since quotient is a small integer), then degree-7 sin /
// degree-8 cos minimax polys over |r| <= pi/4, then branch-free quadrant
// selection per lane.
__device__ __forceinline__ void sincos2(float a0, float a1, u64& s_out, u64& c_out) {
    const float TWO_OVER_PI = 0.63661977236758134308f;
    float j0 = rintf(a0 * TWO_OVER_PI);
    float j1 = rintf(a1 * TWO_OVER_PI);
    int i0 = (int)j0, i1 = (int)j1;
    u64 j2 = pack2(j0, j1);
    u64 r2 = fma2(j2, K2(-1.5707962513e+00f), pack2(a0, a1));
    r2 = fma2(j2, K2(-7.5497894159e-08f), r2);
    r2 = fma2(j2, K2(-5.3903029534e-15f), r2);
    u64 z = mul2(r2, r2);
    // sin(r) = r + r*z*(S1 + z*(S2 + z*S3))
    u64 p = fma2(z, K2(-1.9515295891e-04f), K2(8.3321608736e-03f));
    p = fma2(p, z, K2(-1.6666654611e-01f));
    u64 rz = mul2(r2, z);
    u64 s = fma2(p, rz, r2);
    // cos(r) = 1 + z*(-0.5 + z*(C1 + z*(C2 + z*C3)))
    u64 q = fma2(z, K2(2.4433157442e-05f), K2(-1.3887316255e-03f));
    q = fma2(q, z, K2(4.1666645683e-02f));
    q = fma2(q, z, K2(-0.5f));
    u64 c = fma2(q, z, K2(1.0f));

    float s0, s1, c0, c1;
    unpack2(s, s0, s1); unpack2(c, c0, c1);
    // quadrant k mod 4: 0:(s,c) 1:(c,-s) 2:(-s,-c) 3:(-c,s)
    float ss0 = (i0 & 1) ? c0 : s0;
    float cs0 = (i0 & 1) ? s0 : c0;
    float ss1 = (i1 & 1) ? c1 : s1;
    float cs1 = (i1 & 1) ? s1 : c1;
    unsigned sg0 = (unsigned)(i0 & 2) << 30, cg0 = (unsigned)((i0 + 1) & 2) << 30;
    unsigned sg1 = (unsigned)(i1 & 2) << 30, cg1 = (unsigned)((i1 + 1) & 2) << 30;
    ss0 = __int_as_float(__float_as_int(ss0) ^ sg0);
    cs0 = __int_as_float(__float_as_int(cs0) ^ cg0);
    ss1 = __int_as_float(__float_as_int(ss1) ^ sg1);
    cs1 = __int_as_float(__float_as_int(cs1) ^ cg1);
    s_out = pack2(ss0, ss1);
    c_out = pack2(cs0, cs1);
}

__global__ void __launch_bounds__(TPB) nerf_fused_kernel(
    const float* __restrict__ x,
    const float* __restrict__ W1,
    const float* __restrict__ b1,
    const float* __restrict__ W2,
    const float* __restrict__ b2,
    float* __restrict__ out, int N)
{
    __shared__ u64 sW1[NIN * HID];   // duplicated (w,w) pairs, 6912 B
    __shared__ u64 sB1[HID];
    __shared__ u64 sW2[HID];
    __shared__ float sB2;

    for (int k = threadIdx.x; k < NIN * HID; k += TPB) {
        float w = W1[k];
        sW1[k] = pack2(w, w);
    }
    if (threadIdx.x < HID) {
        float v = b1[threadIdx.x]; sB1[threadIdx.x] = pack2(v, v);
        float w = W2[threadIdx.x]; sW2[threadIdx.x] = pack2(w, w);
    }
    if (threadIdx.x == 0) sB2 = b2[0];
    __syncthreads();

    int t = blockIdx.x * TPB + threadIdx.x;
    long long p = 2LL * t;
    if (p >= N) return;
    bool full = (p + 1 < N);

    float x0, y0, z0, x1, y1, z1;
    if (full) {
        const float2* xv = (const float2*)x;   // 2 points = 6 floats = 3 float2, 8B-aligned
        float2 a = xv[3 * t];
        float2 bq = xv[3 * t + 1];
        float2 cq = xv[3 * t + 2];
        x0 = a.x; y0 = a.y; z0 = bq.x; x1 = bq.y; y1 = cq.x; z1 = cq.y;
    } else {
        x0 = x[p * 3]; y0 = x[p * 3 + 1]; z0 = x[p * 3 + 2];
        x1 = x0; y1 = y0; z1 = z0;
    }

    // freq bands: 2^linspace(0,10,4) in fp32; exp2f matches numpy to <=1-2 ulp,
    // and the dominant band 1024 is exact.
    const float f1 = exp2f(3.3333333333333335f);
    const float f2 = exp2f(6.666666666666667f);
    const float fr1 = 1.0f;

    u64 tf[NIN];
    tf[0] = pack2(x0, x1);
    tf[1] = pack2(y0, y1);
    tf[2] = pack2(z0, z1);
    // t layout: [x(3), then per freq f: sin_xyz(3), cos_xyz(3)]
    {
        float fv;
        fv = fr1;
        sincos2(x0 * fv, x1 * fv, tf[3 + 0], tf[3 + 3]);
        sincos2(y0 * fv, y1 * fv, tf[3 + 1], tf[3 + 4]);
        sincos2(z0 * fv, z1 * fv, tf[3 + 2], tf[3 + 5]);
        fv = f1;
        sincos2(x0 * fv, x1 * fv, tf[9 + 0], tf[9 + 3]);
        sincos2(y0 * fv, y1 * fv, tf[9 + 1], tf[9 + 4]);
        sincos2(z0 * fv, z1 * fv, tf[9 + 2], tf[9 + 5]);
        fv = f2;
        sincos2(x0 * fv, x1 * fv, tf[15 + 0], tf[15 + 3]);
        sincos2(y0 * fv, y1 * fv, tf[15 + 1], tf[15 + 4]);
        sincos2(z0 * fv, z1 * fv, tf[15 + 2], tf[15 + 5]);
        fv = 1024.0f;
        sincos2(x0 * fv, x1 * fv, tf[21 + 0], tf[21 + 3]);
        sincos2(y0 * fv, y1 * fv, tf[21 + 1], tf[21 + 4]);
        sincos2(z0 * fv, z1 * fv, tf[21 + 2], tf[21 + 5]);
    }

    // Fused MLP: for each hidden unit j, h = relu(dot(t, W1[:,j]) + b1[j]);
    // acc += h * W2[j].  Only one h alive at a time -> low register pressure.
    u64 acc = K2(0.0f);
    #pragma unroll 8
    for (int j = 0; j < HID; j++) {
        u64 h = sB1[j];
        #pragma unroll
        for (int i = 0; i < NIN; i++) {
            h = fma2(tf[i], sW1[i * HID + j], h);
        }
        float h0, h1; unpack2(h, h0, h1);
        h0 = fmaxf(h0, 0.0f);
        h1 = fmaxf(h1, 0.0f);
        acc = fma2(pack2(h0, h1), sW2[j], acc);
    }

    float o0, o1; unpack2(acc, o0, o1);
    float bb = sB2;
    o0 = fmaxf(o0 + bb, 0.0f);
    o1 = fmaxf(o1 + bb, 0.0f);
    if (full) {
        ((float2*)out)[t] = make_float2(o0, o1);
    } else {
        out[p] = o0;
    }
}

extern "C" void kernel_launch(void* const* d_in, const int* in_sizes, int n_in,
                              void* d_out, int out_size) {
    const float* x  = (const float*)d_in[0];
    const float* W1 = (const float*)d_in[1];
    const float* b1 = (const float*)d_in[2];
    const float* W2 = (const float*)d_in[3];
    const float* b2 = (const float*)d_in[4];
    float* out = (float*)d_out;

    int N = in_sizes[0] / 3;
    int pairs = (N + 1) / 2;
    int blocks = (pairs + TPB - 1) / TPB;
    nerf_fused_kernel<<<blocks, TPB>>>(x, W1, b1, W2, b2, out, N);
}